// round 12
// baseline (speedup 1.0000x reference)
#include <cuda_runtime.h>
#include <cstdint>

#define T_STEPS 1024
#define B_      64
#define D_      512
#define H_      512

// ---------------- persistent kernel config --------------------
#define G_CTAS   64
#define S_COLS   8
#define NTHREADS 256                  // 8 warps: 4 row-groups x 2 k-halves
#define N_BLK    4                    // k-blocks of 128 h-columns
#define AS_BLK_FLOATS (B_ * 128)      // 8192 floats per k-block (global h layout)

#define WP_FLOATS 16384               // 64 KB recurrent weights (B-fragment order)
#define SM_WP_OFF   0
#define SM_PB_OFF   (WP_FLOATS * 4)                           // 65536
#define PB_STRIDE   20                                        // floats, pad vs conflicts
#define SMEM_BYTES  (SM_PB_OFF + 2 * 128 * PB_STRIDE * 4)     // 86016 B

// ---------------- gemm kernel config --------------------------
#define GM_AS   (128 * 36)
#define GM_BS   (32 * 72)
#define GM_SMEM ((2 * GM_AS + 2 * GM_BS) * 4)

// ---------------- device globals ------------------------------
__device__ __align__(256) float    g_xp[(size_t)T_STEPS * B_ * 4 * H_];
__device__ __align__(256) float    g_hblk[3][N_BLK][AS_BLK_FLOATS];  // triple buffer
__device__ __align__(256) unsigned g_flags[G_CTAS * 32];             // 1 per 128B line

// ---------------- helpers -------------------------------------
__device__ __forceinline__ float tf32r(float x) {
    unsigned r;
    asm("cvt.rna.tf32.f32 %0, %1;" : "=r"(r) : "f"(x));
    return __uint_as_float(r);
}
__device__ __forceinline__ float sigm_(float x) {
    return __fdividef(1.0f, 1.0f + __expf(-x));
}
__device__ __forceinline__ float tanh_(float x) {
    float a = fabsf(x);
    float e = __expf(-2.0f * a);
    float r = __fdividef(1.0f - e, 1.0f + e);
    return copysignf(r, x);
}
__device__ __forceinline__ void mma8(float* acc, unsigned a0, unsigned a1,
                                     unsigned a2, unsigned a3,
                                     unsigned b0, unsigned b1) {
    asm volatile(
        "mma.sync.aligned.m16n8k8.row.col.f32.tf32.tf32.f32 "
        "{%0,%1,%2,%3}, {%4,%5,%6,%7}, {%8,%9}, {%0,%1,%2,%3};"
        : "+f"(acc[0]), "+f"(acc[1]), "+f"(acc[2]), "+f"(acc[3])
        : "r"(a0), "r"(a1), "r"(a2), "r"(a3), "r"(b0), "r"(b1));
}
__device__ __forceinline__ unsigned ld_acq(const unsigned* p) {
    unsigned v;
    asm volatile("ld.acquire.gpu.global.u32 %0, [%1];"
                 : "=r"(v) : "l"(p) : "memory");
    return v;
}
__device__ __forceinline__ void st_rel(unsigned* p, unsigned v) {
    asm volatile("st.release.gpu.global.u32 [%0], %1;"
                 :: "l"(p), "r"(v) : "memory");
}
// h storage: within a 128-col block, position kb+2t holds k=kb+t,
// position kb+2t+1 holds k=kb+t+4 (A frag = one 8B load), XOR-swizzled
// by (row&7)<<3. (R7-R11 verified.)
__device__ __forceinline__ int hpos(int row, int col) {
    int o = col & 127;
    int j = o & 7;
    int p = (o & ~7) | ((j < 4) ? (2 * j) : (2 * (j - 4) + 1));
    return row * 128 + (p ^ ((row & 7) << 3));
}

// ---------------- x-projection GEMM + fused init (R9-proven) --
__global__ void __launch_bounds__(256, 2)
xproj_gemm(const float* __restrict__ x,  const float* __restrict__ h0,
           const float* __restrict__ Wii, const float* __restrict__ Wif,
           const float* __restrict__ Wig, const float* __restrict__ Wio,
           const float* __restrict__ bi,  const float* __restrict__ bf,
           const float* __restrict__ bg,  const float* __restrict__ bo)
{
    extern __shared__ float sm[];
    float* As = sm;
    float* Bs = sm + 2 * GM_AS;

    const int tid  = threadIdx.x;

    if (blockIdx.y == 0) {
        unsigned t0 = blockIdx.x * 256 + tid;
        for (unsigned i = t0; i < G_CTAS * 32; i += 8192) g_flags[i] = 0;
        for (unsigned i = t0; i < B_ * H_; i += 8192) {
            int row = i >> 9, col = i & 511;
            g_hblk[0][col >> 7][hpos(row, col)] = tf32r(h0[i]);
        }
    }

    const int lane = tid & 31;
    const int wid  = tid >> 5;
    const int wm   = wid & 3;
    const int wn   = wid >> 2;
    const int g    = lane >> 2;
    const int t    = lane & 3;

    const int nb = blockIdx.x * 64;
    const int mb = blockIdx.y * 128;
    const int gate = nb >> 9;
    const int colb = nb & 511;

    const float* Wg = (gate == 0) ? Wii : (gate == 1) ? Wif : (gate == 2) ? Wig : Wio;
    const float* bv = (gate == 0) ? bi  : (gate == 1) ? bf  : (gate == 2) ? bg  : bo;

    float acc[2][4][4];
    #pragma unroll
    for (int nt4 = 0; nt4 < 4; ++nt4) {
        float b0 = bv[colb + wn * 32 + nt4 * 8 + 2 * t];
        float b1 = bv[colb + wn * 32 + nt4 * 8 + 2 * t + 1];
        #pragma unroll
        for (int mt = 0; mt < 2; ++mt) {
            acc[mt][nt4][0] = b0; acc[mt][nt4][1] = b1;
            acc[mt][nt4][2] = b0; acc[mt][nt4][3] = b1;
        }
    }

    float4 ra[4], rb[2];
    auto ldAB = [&](int it) {
        #pragma unroll
        for (int i = 0; i < 4; ++i) {
            int idx = tid + i * 256;
            int row = idx >> 3, j4 = idx & 7;
            ra[i] = *reinterpret_cast<const float4*>(
                x + (size_t)(mb + row) * 512 + it * 32 + j4 * 4);
        }
        #pragma unroll
        for (int i = 0; i < 2; ++i) {
            int idx = tid + i * 256;
            int kr = idx >> 4, j4 = idx & 15;
            rb[i] = *reinterpret_cast<const float4*>(
                Wg + (size_t)(it * 32 + kr) * 512 + colb + j4 * 4);
        }
    };
    auto stAB = [&](int buf) {
        #pragma unroll
        for (int i = 0; i < 4; ++i) {
            int idx = tid + i * 256;
            int row = idx >> 3, j4 = idx & 7;
            float4 v = ra[i];
            v.x = tf32r(v.x); v.y = tf32r(v.y); v.z = tf32r(v.z); v.w = tf32r(v.w);
            *reinterpret_cast<float4*>(As + buf * GM_AS + row * 36 + j4 * 4) = v;
        }
        #pragma unroll
        for (int i = 0; i < 2; ++i) {
            int idx = tid + i * 256;
            int kr = idx >> 4, j4 = idx & 15;
            float4 v = rb[i];
            v.x = tf32r(v.x); v.y = tf32r(v.y); v.z = tf32r(v.z); v.w = tf32r(v.w);
            *reinterpret_cast<float4*>(Bs + buf * GM_BS + kr * 72 + j4 * 4) = v;
        }
    };

    ldAB(0);
    stAB(0);
    __syncthreads();

    #pragma unroll 1
    for (int it = 0; it < 16; ++it) {
        if (it < 15) ldAB(it + 1);
        const float* Ab = As + (it & 1) * GM_AS;
        const float* Bb = Bs + (it & 1) * GM_BS;
        #pragma unroll
        for (int ks = 0; ks < 4; ++ks) {
            const int kb = ks * 8;
            unsigned a[2][4], b[4][2];
            #pragma unroll
            for (int mt = 0; mt < 2; ++mt) {
                int rowb = wm * 32 + mt * 16;
                a[mt][0] = __float_as_uint(Ab[(rowb + g)     * 36 + kb + t]);
                a[mt][1] = __float_as_uint(Ab[(rowb + g + 8) * 36 + kb + t]);
                a[mt][2] = __float_as_uint(Ab[(rowb + g)     * 36 + kb + t + 4]);
                a[mt][3] = __float_as_uint(Ab[(rowb + g + 8) * 36 + kb + t + 4]);
            }
            #pragma unroll
            for (int nt4 = 0; nt4 < 4; ++nt4) {
                int cb = wn * 32 + nt4 * 8 + g;
                b[nt4][0] = __float_as_uint(Bb[(kb + t)     * 72 + cb]);
                b[nt4][1] = __float_as_uint(Bb[(kb + t + 4) * 72 + cb]);
            }
            #pragma unroll
            for (int mt = 0; mt < 2; ++mt)
                #pragma unroll
                for (int nt4 = 0; nt4 < 4; ++nt4)
                    mma8(acc[mt][nt4], a[mt][0], a[mt][1], a[mt][2], a[mt][3],
                         b[nt4][0], b[nt4][1]);
        }
        if (it < 15) {
            stAB((it + 1) & 1);
            __syncthreads();
        }
    }

    #pragma unroll
    for (int mt = 0; mt < 2; ++mt) {
        #pragma unroll
        for (int nt4 = 0; nt4 < 4; ++nt4) {
            int row0 = mb + wm * 32 + mt * 16 + g;
            int col  = nb + wn * 32 + nt4 * 8 + 2 * t;
            *reinterpret_cast<float2*>(g_xp + (size_t)row0 * 2048 + col) =
                make_float2(acc[mt][nt4][0], acc[mt][nt4][1]);
            *reinterpret_cast<float2*>(g_xp + (size_t)(row0 + 8) * 2048 + col) =
                make_float2(acc[mt][nt4][2], acc[mt][nt4][3]);
        }
    }
}

// ---------------- persistent LSTM kernel ----------------------
// 8 warps, k-split; A-fragments loaded DIRECTLY from L2 (__ldcg) in a
// depth-2 register chunk pipeline — no cp.async, no smem h staging.
__global__ void __launch_bounds__(NTHREADS, 1)
lstm_persist(const float* __restrict__ c0,
             const float* __restrict__ Whi, const float* __restrict__ Whf,
             const float* __restrict__ Whg, const float* __restrict__ Who,
             float* __restrict__ out)
{
    extern __shared__ char smem_raw[];
    float* Wp   = reinterpret_cast<float*>(smem_raw + SM_WP_OFF);
    float* Pbuf = reinterpret_cast<float*>(smem_raw + SM_PB_OFF);

    const int tid  = threadIdx.x;
    const int wid  = tid >> 5;
    const int lane = tid & 31;
    const int half = wid >> 2;          // 0: k[0,256), 1: k[256,512)
    const int wrow = wid & 3;           // row-group: rows [wrow*16, wrow*16+16)
    const int g    = lane >> 2;
    const int t    = lane & 3;
    const int cta  = blockIdx.x;

    // one-time: stage recurrent weight slice, tf32, B-fragment order
    {
        const float* Wh[4] = {Whi, Whf, Whg, Who};
        for (int e = tid; e < WP_FLOATS; e += NTHREADS) {
            int j   = e & 1;
            int ln  = (e >> 1) & 31;
            int nt  = (e >> 6) & 3;
            int ksg = e >> 8;
            int jj  = ln >> 2;
            int k   = ksg * 8 + (ln & 3) + 4 * j;
            int col = cta * S_COLS + jj;
            Wp[e] = tf32r(Wh[nt][k * H_ + col]);
        }
    }

    const int col0 = cta * S_COLS + 2 * t;
    const int rb0  = wrow * 16 + g;
    const int rb1  = rb0 + 8;

    float creg[4];
    float2 xpre[4][2];
    if (half == 0) {
        creg[0] = c0[rb0 * H_ + col0];
        creg[1] = c0[rb0 * H_ + col0 + 1];
        creg[2] = c0[rb1 * H_ + col0];
        creg[3] = c0[rb1 * H_ + col0 + 1];
        #pragma unroll
        for (int nt = 0; nt < 4; ++nt) {
            xpre[nt][0] = __ldcs(reinterpret_cast<const float2*>(
                g_xp + (size_t)rb0 * 2048 + nt * 512 + col0));
            xpre[nt][1] = __ldcs(reinterpret_cast<const float2*>(
                g_xp + (size_t)rb1 * 2048 + nt * 512 + col0));
        }
    }

    __syncthreads();   // Wp ready

    const unsigned* WpU = reinterpret_cast<const unsigned*>(Wp);
    const int swz  = g << 3;
    const int pidx = wrow * 32 + lane;  // partial-buffer slot (matches across halves)

    int cur = 0;                        // step % 3
    #pragma unroll 1
    for (int step = 0; step < T_STEPS; ++step) {
        const int nxt = (cur == 2) ? 0 : cur + 1;
        const float* hsrc  = &g_hblk[cur][0][0];
        float*       hnext = &g_hblk[nxt][0][0];
        const unsigned want = (unsigned)step;

        // poll this half's gating CTAs (one 32-flag round per warp)
        {
            int src_cta = half * 32 + lane;
            bool skip = (src_cta == cta);
            bool done;
            do {
                unsigned v = skip ? ~0u : ld_acq(&g_flags[src_cta * 32]);
                done = __all_sync(0xffffffffu, v >= want);
            } while (!done);
        }

        // A-fragment chunk loader: chunk c covers ksg = half*32 + c*8 + i,
        // global block = half*2 + (c>>1), kstep-in-block = (c&1)*8 + i.
        // Addresses identical to the R11 smem reader (layout-preserving).
        #define LDCHUNK(c, bA, bB)                                            \
        do {                                                                  \
            const float* _base = hsrc + (half * 2 + ((c) >> 1)) * AS_BLK_FLOATS; \
            _Pragma("unroll")                                                 \
            for (int _i = 0; _i < 8; ++_i) {                                  \
                int _off = (((((c) & 1) * 8 + _i) * 8 + 2 * t) ^ swz);        \
                (bA)[_i] = __ldcg(reinterpret_cast<const float2*>(            \
                    _base + rb0 * 128 + _off));                               \
                (bB)[_i] = __ldcg(reinterpret_cast<const float2*>(            \
                    _base + rb1 * 128 + _off));                               \
            }                                                                 \
        } while (0)

        float2 A0[8], B0[8], A1[8], B1[8];
        LDCHUNK(0, A0, B0);
        LDCHUNK(1, A1, B1);

        // acc init: half 0 from x_proj (bias folded), half 1 zero
        float acc[4][4];
        if (half == 0) {
            #pragma unroll
            for (int nt = 0; nt < 4; ++nt) {
                acc[nt][0] = xpre[nt][0].x; acc[nt][1] = xpre[nt][0].y;
                acc[nt][2] = xpre[nt][1].x; acc[nt][3] = xpre[nt][1].y;
            }
            if (step + 1 < T_STEPS) {   // prefetch next step's x_proj
                const float* xpn = g_xp + (size_t)(step + 1) * B_ * 2048;
                #pragma unroll
                for (int nt = 0; nt < 4; ++nt) {
                    xpre[nt][0] = __ldcs(reinterpret_cast<const float2*>(
                        xpn + (size_t)rb0 * 2048 + nt * 512 + col0));
                    xpre[nt][1] = __ldcs(reinterpret_cast<const float2*>(
                        xpn + (size_t)rb1 * 2048 + nt * 512 + col0));
                }
            }
        } else {
            #pragma unroll
            for (int nt = 0; nt < 4; ++nt)
                #pragma unroll
                for (int ci = 0; ci < 4; ++ci) acc[nt][ci] = 0.0f;
        }

        // mma over 4 chunks of 8 ksteps; refill consumed buffer with c+2
        #pragma unroll
        for (int c = 0; c < 4; ++c) {
            float2* bA = (c & 1) ? A1 : A0;
            float2* bB = (c & 1) ? B1 : B0;
            #pragma unroll
            for (int i = 0; i < 8; ++i) {
                const int ksg = half * 32 + c * 8 + i;
                unsigned a0 = __float_as_uint(bA[i].x);
                unsigned a2 = __float_as_uint(bA[i].y);
                unsigned a1 = __float_as_uint(bB[i].x);
                unsigned a3 = __float_as_uint(bB[i].y);
                #pragma unroll
                for (int nt = 0; nt < 4; ++nt) {
                    uint2 b2 = *reinterpret_cast<const uint2*>(
                        WpU + ((size_t)(ksg * 4 + nt) * 32 + lane) * 2);
                    mma8(acc[nt], a0, a1, a2, a3, b2.x, b2.y);
                }
            }
            if (c == 0)      LDCHUNK(2, A0, B0);
            else if (c == 1) LDCHUNK(3, A1, B1);
        }
        #undef LDCHUNK

        // half 1: deposit partials (double-buffered, padded, float4)
        float* pb = Pbuf + (step & 1) * 128 * PB_STRIDE + pidx * PB_STRIDE;
        if (half == 1) {
            #pragma unroll
            for (int nt = 0; nt < 4; ++nt)
                *reinterpret_cast<float4*>(pb + nt * 4) =
                    make_float4(acc[nt][0], acc[nt][1], acc[nt][2], acc[nt][3]);
        }

        __syncthreads();   // partials(step) visible; rendezvous of both halves

        if (half == 0) {
            // reduce + epilogue
            #pragma unroll
            for (int nt = 0; nt < 4; ++nt) {
                float4 p = *reinterpret_cast<const float4*>(pb + nt * 4);
                acc[nt][0] += p.x; acc[nt][1] += p.y;
                acc[nt][2] += p.z; acc[nt][3] += p.w;
            }
            #pragma unroll
            for (int ci = 0; ci < 4; ++ci) {
                const int rb  = (ci >= 2) ? rb1 : rb0;
                const int col = col0 + (ci & 1);
                float iv = sigm_(acc[0][ci]);
                float fv = sigm_(acc[1][ci]);
                float gv = tanh_(acc[2][ci]);
                float ov = sigm_(acc[3][ci]);
                float c  = fv * creg[ci] + iv * gv;
                creg[ci] = c;
                float h  = ov * tanh_(c);
                __stcg(hnext + (col >> 7) * AS_BLK_FLOATS + hpos(rb, col), tf32r(h));
                if (step == T_STEPS - 1) {
                    out[rb * H_ + col]           = h;
                    out[B_ * H_ + rb * H_ + col] = c;
                }
            }
            // publish: HB among warps 0-3, then one fence + release flag
            asm volatile("bar.sync 1, 128;" ::: "memory");
            if (tid == 0) {
                __threadfence();
                st_rel(&g_flags[cta * 32], (unsigned)(step + 1));
            }
        }

        cur = nxt;
    }
}

// ---------------- launch --------------------------------------
extern "C" void kernel_launch(void* const* d_in, const int* in_sizes, int n_in,
                              void* d_out, int out_size)
{
    const float* x   = (const float*)d_in[0];
    const float* h0  = (const float*)d_in[1];
    const float* c0  = (const float*)d_in[2];
    const float* Wii = (const float*)d_in[3];
    const float* Whi = (const float*)d_in[4];
    const float* bi  = (const float*)d_in[5];
    const float* Wif = (const float*)d_in[6];
    const float* Whf = (const float*)d_in[7];
    const float* bf  = (const float*)d_in[8];
    const float* Wig = (const float*)d_in[9];
    const float* Whg = (const float*)d_in[10];
    const float* bg  = (const float*)d_in[11];
    const float* Wio = (const float*)d_in[12];
    const float* Who = (const float*)d_in[13];
    const float* bo  = (const float*)d_in[14];
    float* out = (float*)d_out;

    cudaFuncSetAttribute(lstm_persist,
                         cudaFuncAttributeMaxDynamicSharedMemorySize, SMEM_BYTES);
    cudaFuncSetAttribute(xproj_gemm,
                         cudaFuncAttributeMaxDynamicSharedMemorySize, GM_SMEM);

    xproj_gemm<<<dim3(32, 512), 256, GM_SMEM>>>(x, h0, Wii, Wif, Wig, Wio,
                                                bi, bf, bg, bo);
    lstm_persist<<<G_CTAS, NTHREADS, SMEM_BYTES>>>(c0, Whi, Whf, Whg, Who, out);
}

// round 13
// speedup vs baseline: 1.0540x; 1.0540x over previous
#include <cuda_runtime.h>
#include <cstdint>

#define T_STEPS 1024
#define B_      64
#define D_      512
#define H_      512

// ---------------- persistent kernel config --------------------
#define G_CTAS   64
#define S_COLS   8
#define NTHREADS 256                  // 8 warps: 4 row-groups x 2 k-halves
#define N_BLK    4
#define KS_PER_BLK 16

#define WP_FLOATS 16384
#define AS_BLK_FLOATS (B_ * 128)

#define SM_WP_OFF   0
#define SM_AS_OFF   (WP_FLOATS * 4)                           // 65536
#define SM_PB_OFF   (SM_AS_OFF + N_BLK * AS_BLK_FLOATS * 4)   // 196608
#define PB_STRIDE   20
#define SMEM_BYTES  (SM_PB_OFF + 2 * 128 * PB_STRIDE * 4)     // 217088 B

// ---------------- xproj v2 config -----------------------------
#define XP_A_FLOATS (128 * 36)        // 4608 floats per stage (stride 36)
#define XP_B_FLOATS (32 * 72)         // 2304 floats per stage (stride 72)
#define XP_STG_FLOATS (XP_A_FLOATS + XP_B_FLOATS)   // 6912
#define XP_STG_BYTES  (XP_STG_FLOATS * 4)           // 27648
#define XP_SMEM       (3 * XP_STG_BYTES)            // 82944 B

// ---------------- device globals ------------------------------
__device__ __align__(256) float    g_xp[(size_t)T_STEPS * B_ * 4 * H_];
__device__ __align__(256) float    g_xtf[(size_t)T_STEPS * B_ * D_];   // tf32 x
__device__ __align__(256) float    g_wxt[4][D_ * H_];                  // tf32 W_x
__device__ __align__(256) float    g_hblk[3][N_BLK][AS_BLK_FLOATS];
__device__ __align__(256) unsigned g_flags[G_CTAS * 32];

// ---------------- helpers -------------------------------------
__device__ __forceinline__ float tf32r(float x) {
    unsigned r;
    asm("cvt.rna.tf32.f32 %0, %1;" : "=r"(r) : "f"(x));
    return __uint_as_float(r);
}
__device__ __forceinline__ float sigm_(float x) {
    return __fdividef(1.0f, 1.0f + __expf(-x));
}
__device__ __forceinline__ float tanh_(float x) {
    float a = fabsf(x);
    float e = __expf(-2.0f * a);
    float r = __fdividef(1.0f - e, 1.0f + e);
    return copysignf(r, x);
}
__device__ __forceinline__ void mma8(float* acc, unsigned a0, unsigned a1,
                                     unsigned a2, unsigned a3,
                                     unsigned b0, unsigned b1) {
    asm volatile(
        "mma.sync.aligned.m16n8k8.row.col.f32.tf32.tf32.f32 "
        "{%0,%1,%2,%3}, {%4,%5,%6,%7}, {%8,%9}, {%0,%1,%2,%3};"
        : "+f"(acc[0]), "+f"(acc[1]), "+f"(acc[2]), "+f"(acc[3])
        : "r"(a0), "r"(a1), "r"(a2), "r"(a3), "r"(b0), "r"(b1));
}
__device__ __forceinline__ void cp16(unsigned dst, const void* src) {
    asm volatile("cp.async.cg.shared.global [%0], [%1], 16;\n"
                 :: "r"(dst), "l"(src) : "memory");
}
__device__ __forceinline__ unsigned ld_acq(const unsigned* p) {
    unsigned v;
    asm volatile("ld.acquire.gpu.global.u32 %0, [%1];"
                 : "=r"(v) : "l"(p) : "memory");
    return v;
}
__device__ __forceinline__ void st_rel(unsigned* p, unsigned v) {
    asm volatile("st.release.gpu.global.u32 [%0], %1;"
                 :: "l"(p), "r"(v) : "memory");
}
__device__ __forceinline__ int hpos(int row, int col) {
    int o = col & 127;
    int j = o & 7;
    int p = (o & ~7) | ((j < 4) ? (2 * j) : (2 * (j - 4) + 1));
    return row * 128 + (p ^ ((row & 7) << 3));
}

// ---------------- cvt_init: tf32 pre-convert + state init -----
__global__ void cvt_init(const float4* __restrict__ x4, const float* __restrict__ h0,
                         const float* __restrict__ Wii, const float* __restrict__ Wif,
                         const float* __restrict__ Wig, const float* __restrict__ Wio)
{
    unsigned tid  = blockIdx.x * blockDim.x + threadIdx.x;
    unsigned nthr = gridDim.x * blockDim.x;

    for (unsigned i = tid; i < G_CTAS * 32; i += nthr) g_flags[i] = 0;
    for (unsigned i = tid; i < B_ * H_; i += nthr) {
        int row = i >> 9, col = i & 511;
        g_hblk[0][col >> 7][hpos(row, col)] = tf32r(h0[i]);
    }

    float4* xo = reinterpret_cast<float4*>(g_xtf);
    const size_t nx4 = (size_t)T_STEPS * B_ * D_ / 4;
    for (size_t i = tid; i < nx4; i += nthr) {
        float4 v = x4[i];
        v.x = tf32r(v.x); v.y = tf32r(v.y); v.z = tf32r(v.z); v.w = tf32r(v.w);
        xo[i] = v;
    }

    const float* Ws[4] = {Wii, Wif, Wig, Wio};
    #pragma unroll
    for (int gt = 0; gt < 4; ++gt) {
        const float4* src = reinterpret_cast<const float4*>(Ws[gt]);
        float4*       dst = reinterpret_cast<float4*>(g_wxt[gt]);
        for (unsigned i = tid; i < (D_ * H_) / 4; i += nthr) {
            float4 v = src[i];
            v.x = tf32r(v.x); v.y = tf32r(v.y); v.z = tf32r(v.z); v.w = tf32r(v.w);
            dst[i] = v;
        }
    }
}

// ---------------- x-projection GEMM v2 (cp.async 3-stage) -----
// C[65536, 2048] = g_xtf[65536,512] * g_wxt[512,2048] + bias -> g_xp
// grid (32, 512): 128x64 tile, K=512 in 16 chunks of 32.
__global__ void __launch_bounds__(256, 2)
xproj_gemm(const float* __restrict__ bi, const float* __restrict__ bf,
           const float* __restrict__ bg, const float* __restrict__ bo)
{
    extern __shared__ float sm[];
    const unsigned smem_base = (unsigned)__cvta_generic_to_shared(sm);

    const int tid  = threadIdx.x;
    const int lane = tid & 31;
    const int wid  = tid >> 5;
    const int wm   = wid & 3;
    const int wn   = wid >> 2;
    const int g    = lane >> 2;
    const int t    = lane & 3;

    const int nb = blockIdx.x * 64;
    const int mb = blockIdx.y * 128;
    const int gate = nb >> 9;
    const int colb = nb & 511;

    const float* Wg = g_wxt[gate];
    const float* bv = (gate == 0) ? bi : (gate == 1) ? bf : (gate == 2) ? bg : bo;

    float acc[2][4][4];
    #pragma unroll
    for (int nt4 = 0; nt4 < 4; ++nt4) {
        float b0 = bv[colb + wn * 32 + nt4 * 8 + 2 * t];
        float b1 = bv[colb + wn * 32 + nt4 * 8 + 2 * t + 1];
        #pragma unroll
        for (int mt = 0; mt < 2; ++mt) {
            acc[mt][nt4][0] = b0; acc[mt][nt4][1] = b1;
            acc[mt][nt4][2] = b0; acc[mt][nt4][3] = b1;
        }
    }

    // issue one k-chunk (it) into stage s via cp.async
    auto issue_stage = [&](int it, int s) {
        unsigned base = smem_base + (unsigned)(s * XP_STG_BYTES);
        // A: 128 rows x 32 floats (8x16B per row), stride 36 floats
        #pragma unroll
        for (int i = 0; i < 4; ++i) {
            int idx = tid + i * 256;
            int row = idx >> 3, j = idx & 7;
            cp16(base + (unsigned)(row * 36 + j * 4) * 4u,
                 g_xtf + (size_t)(mb + row) * 512 + it * 32 + j * 4);
        }
        // B: 32 k-rows x 64 floats (16x16B per row), stride 72 floats
        #pragma unroll
        for (int i = 0; i < 2; ++i) {
            int idx = tid + i * 256;
            int kr = idx >> 4, j = idx & 15;
            cp16(base + (unsigned)(XP_A_FLOATS + kr * 72 + j * 4) * 4u,
                 Wg + (size_t)(it * 32 + kr) * 512 + colb + j * 4);
        }
        asm volatile("cp.async.commit_group;\n" ::: "memory");
    };

    issue_stage(0, 0);
    issue_stage(1, 1);
    issue_stage(2, 2);

    #pragma unroll 1
    for (int it = 0; it < 16; ++it) {
        asm volatile("cp.async.wait_group 2;\n" ::: "memory");
        __syncthreads();

        const float* Ab = sm + (it % 3) * XP_STG_FLOATS;
        const float* Bb = Ab + XP_A_FLOATS;
        #pragma unroll
        for (int ks = 0; ks < 4; ++ks) {
            const int kb = ks * 8;
            unsigned a[2][4], b[4][2];
            #pragma unroll
            for (int mt = 0; mt < 2; ++mt) {
                int rowb = wm * 32 + mt * 16;
                a[mt][0] = __float_as_uint(Ab[(rowb + g)     * 36 + kb + t]);
                a[mt][1] = __float_as_uint(Ab[(rowb + g + 8) * 36 + kb + t]);
                a[mt][2] = __float_as_uint(Ab[(rowb + g)     * 36 + kb + t + 4]);
                a[mt][3] = __float_as_uint(Ab[(rowb + g + 8) * 36 + kb + t + 4]);
            }
            #pragma unroll
            for (int nt4 = 0; nt4 < 4; ++nt4) {
                int cb = wn * 32 + nt4 * 8 + g;
                b[nt4][0] = __float_as_uint(Bb[(kb + t)     * 72 + cb]);
                b[nt4][1] = __float_as_uint(Bb[(kb + t + 4) * 72 + cb]);
            }
            #pragma unroll
            for (int mt = 0; mt < 2; ++mt)
                #pragma unroll
                for (int nt4 = 0; nt4 < 4; ++nt4)
                    mma8(acc[mt][nt4], a[mt][0], a[mt][1], a[mt][2], a[mt][3],
                         b[nt4][0], b[nt4][1]);
        }

        if (it + 3 < 16) {
            __syncthreads();          // all warps done reading stage it%3
            issue_stage(it + 3, it % 3);
        }
    }

    #pragma unroll
    for (int mt = 0; mt < 2; ++mt) {
        #pragma unroll
        for (int nt4 = 0; nt4 < 4; ++nt4) {
            int row0 = mb + wm * 32 + mt * 16 + g;
            int col  = nb + wn * 32 + nt4 * 8 + 2 * t;
            *reinterpret_cast<float2*>(g_xp + (size_t)row0 * 2048 + col) =
                make_float2(acc[mt][nt4][0], acc[mt][nt4][1]);
            *reinterpret_cast<float2*>(g_xp + (size_t)(row0 + 8) * 2048 + col) =
                make_float2(acc[mt][nt4][2], acc[mt][nt4][3]);
        }
    }
}

// ---------------- persistent LSTM kernel (R11-proven) ---------
__global__ void __launch_bounds__(NTHREADS, 1)
lstm_persist(const float* __restrict__ c0,
             const float* __restrict__ Whi, const float* __restrict__ Whf,
             const float* __restrict__ Whg, const float* __restrict__ Who,
             float* __restrict__ out)
{
    extern __shared__ char smem_raw[];
    float* Wp   = reinterpret_cast<float*>(smem_raw + SM_WP_OFF);
    float* Asb  = reinterpret_cast<float*>(smem_raw + SM_AS_OFF);
    float* Pbuf = reinterpret_cast<float*>(smem_raw + SM_PB_OFF);

    const int tid  = threadIdx.x;
    const int wid  = tid >> 5;
    const int lane = tid & 31;
    const int half = wid >> 2;
    const int wrow = wid & 3;
    const int g    = lane >> 2;
    const int t    = lane & 3;
    const int cta  = blockIdx.x;

    const unsigned as_base = (unsigned)__cvta_generic_to_shared(smem_raw) + SM_AS_OFF;

    {
        const float* Wh[4] = {Whi, Whf, Whg, Who};
        for (int e = tid; e < WP_FLOATS; e += NTHREADS) {
            int j   = e & 1;
            int ln  = (e >> 1) & 31;
            int nt  = (e >> 6) & 3;
            int ksg = e >> 8;
            int jj  = ln >> 2;
            int k   = ksg * 8 + (ln & 3) + 4 * j;
            int col = cta * S_COLS + jj;
            Wp[e] = tf32r(Wh[nt][k * H_ + col]);
        }
    }

    const int col0 = cta * S_COLS + 2 * t;
    const int rb0  = wrow * 16 + g;
    const int rb1  = rb0 + 8;

    float creg[4];
    float2 xpre[4][2];
    if (half == 0) {
        creg[0] = c0[rb0 * H_ + col0];
        creg[1] = c0[rb0 * H_ + col0 + 1];
        creg[2] = c0[rb1 * H_ + col0];
        creg[3] = c0[rb1 * H_ + col0 + 1];
        #pragma unroll
        for (int nt = 0; nt < 4; ++nt) {
            xpre[nt][0] = __ldcs(reinterpret_cast<const float2*>(
                g_xp + (size_t)rb0 * 2048 + nt * 512 + col0));
            xpre[nt][1] = __ldcs(reinterpret_cast<const float2*>(
                g_xp + (size_t)rb1 * 2048 + nt * 512 + col0));
        }
    }

    __syncthreads();

    const unsigned* WpU = reinterpret_cast<const unsigned*>(Wp);
    const int swz  = g << 3;
    const int pidx = wrow * 32 + lane;

    int cur = 0;
    #pragma unroll 1
    for (int step = 0; step < T_STEPS; ++step) {
        const int nxt = (cur == 2) ? 0 : cur + 1;
        const float* hsrc  = &g_hblk[cur][0][0];
        float*       hnext = &g_hblk[nxt][0][0];
        const unsigned want = (unsigned)step;

        // consume xpre into acc, then launch next-step prefetch so the
        // LDGs are in flight during the poll spin below
        float acc[4][4];
        if (half == 0) {
            #pragma unroll
            for (int nt = 0; nt < 4; ++nt) {
                acc[nt][0] = xpre[nt][0].x; acc[nt][1] = xpre[nt][0].y;
                acc[nt][2] = xpre[nt][1].x; acc[nt][3] = xpre[nt][1].y;
            }
            if (step + 1 < T_STEPS) {
                const float* xpn = g_xp + (size_t)(step + 1) * B_ * 2048;
                #pragma unroll
                for (int nt = 0; nt < 4; ++nt) {
                    xpre[nt][0] = __ldcs(reinterpret_cast<const float2*>(
                        xpn + (size_t)rb0 * 2048 + nt * 512 + col0));
                    xpre[nt][1] = __ldcs(reinterpret_cast<const float2*>(
                        xpn + (size_t)rb1 * 2048 + nt * 512 + col0));
                }
            }
        } else {
            #pragma unroll
            for (int nt = 0; nt < 4; ++nt)
                #pragma unroll
                for (int ci = 0; ci < 4; ++ci) acc[nt][ci] = 0.0f;
        }

        // poll this half's gating CTAs
        {
            int src_cta = half * 32 + lane;
            bool skip = (src_cta == cta);
            bool done;
            do {
                unsigned v = skip ? ~0u : ld_acq(&g_flags[src_cta * 32]);
                done = __all_sync(0xffffffffu, v >= want);
            } while (!done);
        }

        // copy this warp's rows of its 2 k-blocks
        #pragma unroll
        for (int i2 = 0; i2 < 2; ++i2) {
            int b = half * 2 + i2;
            const float* src = hsrc + b * AS_BLK_FLOATS + wrow * 16 * 128;
            unsigned     dst = as_base + (unsigned)b * 32768u
                               + (unsigned)(wrow * 16 * 128) * 4u;
            #pragma unroll
            for (int i = 0; i < 16; ++i) {
                int off = (i * 32 + lane) * 4;
                cp16(dst + (unsigned)off * 4u, src + off);
            }
            asm volatile("cp.async.commit_group;\n" ::: "memory");
        }

        // mma over this warp's 2 k-blocks
        #pragma unroll
        for (int i2 = 0; i2 < 2; ++i2) {
            if (i2 == 0) asm volatile("cp.async.wait_group 1;\n" ::: "memory");
            else         asm volatile("cp.async.wait_group 0;\n" ::: "memory");
            const int blk = half * 2 + i2;
            const float* Ab = Asb + blk * AS_BLK_FLOATS;
            #pragma unroll 4
            for (int ks = 0; ks < KS_PER_BLK; ++ks) {
                const int kb = ks * 8;
                const int ksg = blk * KS_PER_BLK + ks;
                float2 aA = *reinterpret_cast<const float2*>(
                    Ab + rb0 * 128 + ((kb + 2 * t) ^ swz));
                float2 aB = *reinterpret_cast<const float2*>(
                    Ab + rb1 * 128 + ((kb + 2 * t) ^ swz));
                unsigned a0 = __float_as_uint(aA.x);
                unsigned a1 = __float_as_uint(aB.x);
                unsigned a2 = __float_as_uint(aA.y);
                unsigned a3 = __float_as_uint(aB.y);
                #pragma unroll
                for (int nt = 0; nt < 4; ++nt) {
                    uint2 b2 = *reinterpret_cast<const uint2*>(
                        WpU + ((size_t)(ksg * 4 + nt) * 32 + lane) * 2);
                    mma8(acc[nt], a0, a1, a2, a3, b2.x, b2.y);
                }
            }
        }

        // half 1: deposit partials
        float* pb = Pbuf + (step & 1) * 128 * PB_STRIDE + pidx * PB_STRIDE;
        if (half == 1) {
            #pragma unroll
            for (int nt = 0; nt < 4; ++nt)
                *reinterpret_cast<float4*>(pb + nt * 4) =
                    make_float4(acc[nt][0], acc[nt][1], acc[nt][2], acc[nt][3]);
        }

        __syncthreads();

        if (half == 0) {
            #pragma unroll
            for (int nt = 0; nt < 4; ++nt) {
                float4 p = *reinterpret_cast<const float4*>(pb + nt * 4);
                acc[nt][0] += p.x; acc[nt][1] += p.y;
                acc[nt][2] += p.z; acc[nt][3] += p.w;
            }
            #pragma unroll
            for (int ci = 0; ci < 4; ++ci) {
                const int rb  = (ci >= 2) ? rb1 : rb0;
                const int col = col0 + (ci & 1);
                float iv = sigm_(acc[0][ci]);
                float fv = sigm_(acc[1][ci]);
                float gv = tanh_(acc[2][ci]);
                float ov = sigm_(acc[3][ci]);
                float c  = fv * creg[ci] + iv * gv;
                creg[ci] = c;
                float h  = ov * tanh_(c);
                __stcg(hnext + (col >> 7) * AS_BLK_FLOATS + hpos(rb, col), tf32r(h));
                if (step == T_STEPS - 1) {
                    out[rb * H_ + col]           = h;
                    out[B_ * H_ + rb * H_ + col] = c;
                }
            }
            asm volatile("bar.sync 1, 128;" ::: "memory");
            if (tid == 0) {
                __threadfence();
                st_rel(&g_flags[cta * 32], (unsigned)(step + 1));
            }
        }

        cur = nxt;
    }
}

// ---------------- launch --------------------------------------
extern "C" void kernel_launch(void* const* d_in, const int* in_sizes, int n_in,
                              void* d_out, int out_size)
{
    const float* x   = (const float*)d_in[0];
    const float* h0  = (const float*)d_in[1];
    const float* c0  = (const float*)d_in[2];
    const float* Wii = (const float*)d_in[3];
    const float* Whi = (const float*)d_in[4];
    const float* bi  = (const float*)d_in[5];
    const float* Wif = (const float*)d_in[6];
    const float* Whf = (const float*)d_in[7];
    const float* bf  = (const float*)d_in[8];
    const float* Wig = (const float*)d_in[9];
    const float* Whg = (const float*)d_in[10];
    const float* bg  = (const float*)d_in[11];
    const float* Wio = (const float*)d_in[12];
    const float* Who = (const float*)d_in[13];
    const float* bo  = (const float*)d_in[14];
    float* out = (float*)d_out;

    cudaFuncSetAttribute(lstm_persist,
                         cudaFuncAttributeMaxDynamicSharedMemorySize, SMEM_BYTES);
    cudaFuncSetAttribute(xproj_gemm,
                         cudaFuncAttributeMaxDynamicSharedMemorySize, XP_SMEM);

    cvt_init<<<2048, 256>>>(reinterpret_cast<const float4*>(x), h0,
                            Wii, Wif, Wig, Wio);
    xproj_gemm<<<dim3(32, 512), 256, XP_SMEM>>>(bi, bf, bg, bo);
    lstm_persist<<<G_CTAS, NTHREADS, SMEM_BYTES>>>(c0, Whi, Whf, Whg, Who, out);
}

// round 14
// speedup vs baseline: 1.1655x; 1.1058x over previous
#include <cuda_runtime.h>
#include <cstdint>

#define T_STEPS 1024
#define B_      64
#define D_      512
#define H_      512

// ---------------- fused kernel config -------------------------
#define P_CTAS   64                   // persist role CTAs
#define X_CTAS   64                   // xproj role CTAs
#define G_TOTAL  (P_CTAS + X_CTAS)    // 128 <= 148 SMs -> co-resident
#define S_COLS   8
#define NTHREADS 256
#define N_BLK    4
#define KS_PER_BLK 16

#define WP_FLOATS 16384
#define AS_BLK_FLOATS (B_ * 128)

#define SM_WP_OFF   0
#define SM_AS_OFF   (WP_FLOATS * 4)                           // 65536
#define SM_PB_OFF   (SM_AS_OFF + N_BLK * AS_BLK_FLOATS * 4)   // 196608
#define PB_STRIDE   20
#define SMEM_BYTES  (SM_PB_OFF + 2 * 128 * PB_STRIDE * 4)     // 217088 B

// xproj tile pipeline (uses low part of the same smem)
#define XP_A_FLOATS (128 * 36)
#define XP_B_FLOATS (32 * 72)
#define XP_STG_FLOATS (XP_A_FLOATS + XP_B_FLOATS)   // 6912
#define XP_STG_BYTES  (XP_STG_FLOATS * 4)           // 27648 (3 stages = 82944)

#define N_SP     (T_STEPS / 2)        // 512 step-pairs
#define TILES_PER_SP 32
#define N_TILES  (N_SP * TILES_PER_SP)  // 16384

// ---------------- device globals ------------------------------
__device__ __align__(256) float    g_xp[(size_t)T_STEPS * B_ * 4 * H_];
__device__ __align__(256) float    g_xtf[(size_t)T_STEPS * B_ * D_];
__device__ __align__(256) float    g_wxt[4][D_ * H_];
__device__ __align__(256) float    g_hblk[3][N_BLK][AS_BLK_FLOATS];
__device__ __align__(256) unsigned g_flags[P_CTAS * 32];
__device__ __align__(256) unsigned g_xpcnt[N_SP];

// ---------------- helpers -------------------------------------
__device__ __forceinline__ float tf32r(float x) {
    unsigned r;
    asm("cvt.rna.tf32.f32 %0, %1;" : "=r"(r) : "f"(x));
    return __uint_as_float(r);
}
__device__ __forceinline__ float sigm_(float x) {
    return __fdividef(1.0f, 1.0f + __expf(-x));
}
__device__ __forceinline__ float tanh_(float x) {
    float a = fabsf(x);
    float e = __expf(-2.0f * a);
    float r = __fdividef(1.0f - e, 1.0f + e);
    return copysignf(r, x);
}
__device__ __forceinline__ void mma8(float* acc, unsigned a0, unsigned a1,
                                     unsigned a2, unsigned a3,
                                     unsigned b0, unsigned b1) {
    asm volatile(
        "mma.sync.aligned.m16n8k8.row.col.f32.tf32.tf32.f32 "
        "{%0,%1,%2,%3}, {%4,%5,%6,%7}, {%8,%9}, {%0,%1,%2,%3};"
        : "+f"(acc[0]), "+f"(acc[1]), "+f"(acc[2]), "+f"(acc[3])
        : "r"(a0), "r"(a1), "r"(a2), "r"(a3), "r"(b0), "r"(b1));
}
__device__ __forceinline__ void cp16(unsigned dst, const void* src) {
    asm volatile("cp.async.cg.shared.global [%0], [%1], 16;\n"
                 :: "r"(dst), "l"(src) : "memory");
}
__device__ __forceinline__ unsigned ld_acq(const unsigned* p) {
    unsigned v;
    asm volatile("ld.acquire.gpu.global.u32 %0, [%1];"
                 : "=r"(v) : "l"(p) : "memory");
    return v;
}
__device__ __forceinline__ void st_rel(unsigned* p, unsigned v) {
    asm volatile("st.release.gpu.global.u32 [%0], %1;"
                 :: "l"(p), "r"(v) : "memory");
}
__device__ __forceinline__ int hpos(int row, int col) {
    int o = col & 127;
    int j = o & 7;
    int p = (o & ~7) | ((j < 4) ? (2 * j) : (2 * (j - 4) + 1));
    return row * 128 + (p ^ ((row & 7) << 3));
}

// ---------------- cvt_init ------------------------------------
__global__ void cvt_init(const float4* __restrict__ x4, const float* __restrict__ h0,
                         const float* __restrict__ Wii, const float* __restrict__ Wif,
                         const float* __restrict__ Wig, const float* __restrict__ Wio)
{
    unsigned tid  = blockIdx.x * blockDim.x + threadIdx.x;
    unsigned nthr = gridDim.x * blockDim.x;

    for (unsigned i = tid; i < P_CTAS * 32; i += nthr) g_flags[i] = 0;
    for (unsigned i = tid; i < N_SP; i += nthr) g_xpcnt[i] = 0;
    for (unsigned i = tid; i < B_ * H_; i += nthr) {
        int row = i >> 9, col = i & 511;
        g_hblk[0][col >> 7][hpos(row, col)] = tf32r(h0[i]);
    }

    float4* xo = reinterpret_cast<float4*>(g_xtf);
    const size_t nx4 = (size_t)T_STEPS * B_ * D_ / 4;
    for (size_t i = tid; i < nx4; i += nthr) {
        float4 v = x4[i];
        v.x = tf32r(v.x); v.y = tf32r(v.y); v.z = tf32r(v.z); v.w = tf32r(v.w);
        xo[i] = v;
    }

    const float* Ws[4] = {Wii, Wif, Wig, Wio};
    #pragma unroll
    for (int gt = 0; gt < 4; ++gt) {
        const float4* src = reinterpret_cast<const float4*>(Ws[gt]);
        float4*       dst = reinterpret_cast<float4*>(g_wxt[gt]);
        for (unsigned i = tid; i < (D_ * H_) / 4; i += nthr) {
            float4 v = src[i];
            v.x = tf32r(v.x); v.y = tf32r(v.y); v.z = tf32r(v.z); v.w = tf32r(v.w);
            dst[i] = v;
        }
    }
}

// ---------------- xproj role: one 128x64 tile -----------------
__device__ __forceinline__ void xproj_tile(
    float* sm, unsigned smem_base, int mb, int nb,
    const float* __restrict__ bi, const float* __restrict__ bf,
    const float* __restrict__ bg, const float* __restrict__ bo)
{
    const int tid  = threadIdx.x;
    const int lane = tid & 31;
    const int wid  = tid >> 5;
    const int wm   = wid & 3;
    const int wn   = wid >> 2;
    const int g    = lane >> 2;
    const int t    = lane & 3;

    const int gate = nb >> 9;
    const int colb = nb & 511;
    const float* Wg = g_wxt[gate];
    const float* bv = (gate == 0) ? bi : (gate == 1) ? bf : (gate == 2) ? bg : bo;

    float acc[2][4][4];
    #pragma unroll
    for (int nt4 = 0; nt4 < 4; ++nt4) {
        float b0 = bv[colb + wn * 32 + nt4 * 8 + 2 * t];
        float b1 = bv[colb + wn * 32 + nt4 * 8 + 2 * t + 1];
        #pragma unroll
        for (int mt = 0; mt < 2; ++mt) {
            acc[mt][nt4][0] = b0; acc[mt][nt4][1] = b1;
            acc[mt][nt4][2] = b0; acc[mt][nt4][3] = b1;
        }
    }

    auto issue_stage = [&](int it, int s) {
        unsigned base = smem_base + (unsigned)(s * XP_STG_BYTES);
        #pragma unroll
        for (int i = 0; i < 4; ++i) {
            int idx = tid + i * 256;
            int row = idx >> 3, j = idx & 7;
            cp16(base + (unsigned)(row * 36 + j * 4) * 4u,
                 g_xtf + (size_t)(mb + row) * 512 + it * 32 + j * 4);
        }
        #pragma unroll
        for (int i = 0; i < 2; ++i) {
            int idx = tid + i * 256;
            int kr = idx >> 4, j = idx & 15;
            cp16(base + (unsigned)(XP_A_FLOATS + kr * 72 + j * 4) * 4u,
                 Wg + (size_t)(it * 32 + kr) * 512 + colb + j * 4);
        }
        asm volatile("cp.async.commit_group;\n" ::: "memory");
    };

    issue_stage(0, 0);
    issue_stage(1, 1);
    issue_stage(2, 2);

    #pragma unroll 1
    for (int it = 0; it < 16; ++it) {
        if (it < 13) asm volatile("cp.async.wait_group 2;\n" ::: "memory");
        else         asm volatile("cp.async.wait_group 0;\n" ::: "memory");
        __syncthreads();

        const float* Ab = sm + (it % 3) * XP_STG_FLOATS;
        const float* Bb = Ab + XP_A_FLOATS;
        #pragma unroll
        for (int ks = 0; ks < 4; ++ks) {
            const int kb = ks * 8;
            unsigned a[2][4], b[4][2];
            #pragma unroll
            for (int mt = 0; mt < 2; ++mt) {
                int rowb = wm * 32 + mt * 16;
                a[mt][0] = __float_as_uint(Ab[(rowb + g)     * 36 + kb + t]);
                a[mt][1] = __float_as_uint(Ab[(rowb + g + 8) * 36 + kb + t]);
                a[mt][2] = __float_as_uint(Ab[(rowb + g)     * 36 + kb + t + 4]);
                a[mt][3] = __float_as_uint(Ab[(rowb + g + 8) * 36 + kb + t + 4]);
            }
            #pragma unroll
            for (int nt4 = 0; nt4 < 4; ++nt4) {
                int cb = wn * 32 + nt4 * 8 + g;
                b[nt4][0] = __float_as_uint(Bb[(kb + t)     * 72 + cb]);
                b[nt4][1] = __float_as_uint(Bb[(kb + t + 4) * 72 + cb]);
            }
            #pragma unroll
            for (int mt = 0; mt < 2; ++mt)
                #pragma unroll
                for (int nt4 = 0; nt4 < 4; ++nt4)
                    mma8(acc[mt][nt4], a[mt][0], a[mt][1], a[mt][2], a[mt][3],
                         b[nt4][0], b[nt4][1]);
        }

        if (it + 3 < 16) {
            __syncthreads();
            issue_stage(it + 3, it % 3);
        }
    }

    #pragma unroll
    for (int mt = 0; mt < 2; ++mt) {
        #pragma unroll
        for (int nt4 = 0; nt4 < 4; ++nt4) {
            int row0 = mb + wm * 32 + mt * 16 + g;
            int col  = nb + wn * 32 + nt4 * 8 + 2 * t;
            *reinterpret_cast<float2*>(g_xp + (size_t)row0 * 2048 + col) =
                make_float2(acc[mt][nt4][0], acc[mt][nt4][1]);
            *reinterpret_cast<float2*>(g_xp + (size_t)(row0 + 8) * 2048 + col) =
                make_float2(acc[mt][nt4][2], acc[mt][nt4][3]);
        }
    }
    __syncthreads();   // all reads/writes of this tile done before stage reuse
}

// ---------------- fused kernel --------------------------------
__global__ void __launch_bounds__(NTHREADS, 1)
lstm_fused(const float* __restrict__ c0,
           const float* __restrict__ Whi, const float* __restrict__ Whf,
           const float* __restrict__ Whg, const float* __restrict__ Who,
           const float* __restrict__ bi,  const float* __restrict__ bf,
           const float* __restrict__ bg,  const float* __restrict__ bo,
           float* __restrict__ out)
{
    extern __shared__ char smem_raw[];

    // ================= xproj role =================
    if (blockIdx.x >= P_CTAS) {
        const int q = blockIdx.x - P_CTAS;
        float* sm = reinterpret_cast<float*>(smem_raw);
        const unsigned smem_base = (unsigned)__cvta_generic_to_shared(smem_raw);
        #pragma unroll 1
        for (int w = q; w < N_TILES; w += X_CTAS) {
            const int sp  = w >> 5;
            const int nbi = w & 31;
            xproj_tile(sm, smem_base, sp * 128, nbi * 64, bi, bf, bg, bo);
            if (threadIdx.x == 0) {
                __threadfence();
                atomicAdd(&g_xpcnt[sp], 1u);
            }
        }
        return;
    }

    // ================= persist role (R11-proven) =================
    float* Wp   = reinterpret_cast<float*>(smem_raw + SM_WP_OFF);
    float* Asb  = reinterpret_cast<float*>(smem_raw + SM_AS_OFF);
    float* Pbuf = reinterpret_cast<float*>(smem_raw + SM_PB_OFF);

    const int tid  = threadIdx.x;
    const int wid  = tid >> 5;
    const int lane = tid & 31;
    const int half = wid >> 2;
    const int wrow = wid & 3;
    const int g    = lane >> 2;
    const int t    = lane & 3;
    const int cta  = blockIdx.x;

    const unsigned as_base = (unsigned)__cvta_generic_to_shared(smem_raw) + SM_AS_OFF;

    {
        const float* Wh[4] = {Whi, Whf, Whg, Who};
        for (int e = tid; e < WP_FLOATS; e += NTHREADS) {
            int j   = e & 1;
            int ln  = (e >> 1) & 31;
            int nt  = (e >> 6) & 3;
            int ksg = e >> 8;
            int jj  = ln >> 2;
            int k   = ksg * 8 + (ln & 3) + 4 * j;
            int col = cta * S_COLS + jj;
            Wp[e] = tf32r(Wh[nt][k * H_ + col]);
        }
    }

    const int col0 = cta * S_COLS + 2 * t;
    const int rb0  = wrow * 16 + g;
    const int rb1  = rb0 + 8;

    float creg[4];
    float2 xpre[4][2];
    if (half == 0) {
        creg[0] = c0[rb0 * H_ + col0];
        creg[1] = c0[rb0 * H_ + col0 + 1];
        creg[2] = c0[rb1 * H_ + col0];
        creg[3] = c0[rb1 * H_ + col0 + 1];
        // gate on x_proj step 0 availability, then prefetch
        while (ld_acq(&g_xpcnt[0]) < (unsigned)TILES_PER_SP) { }
        #pragma unroll
        for (int nt = 0; nt < 4; ++nt) {
            xpre[nt][0] = __ldcs(reinterpret_cast<const float2*>(
                g_xp + (size_t)rb0 * 2048 + nt * 512 + col0));
            xpre[nt][1] = __ldcs(reinterpret_cast<const float2*>(
                g_xp + (size_t)rb1 * 2048 + nt * 512 + col0));
        }
    }

    __syncthreads();

    const unsigned* WpU = reinterpret_cast<const unsigned*>(Wp);
    const int swz  = g << 3;
    const int pidx = wrow * 32 + lane;

    int cur = 0;
    #pragma unroll 1
    for (int step = 0; step < T_STEPS; ++step) {
        const int nxt = (cur == 2) ? 0 : cur + 1;
        const float* hsrc  = &g_hblk[cur][0][0];
        float*       hnext = &g_hblk[nxt][0][0];
        const unsigned want = (unsigned)step;

        float acc[4][4];
        if (half == 0) {
            #pragma unroll
            for (int nt = 0; nt < 4; ++nt) {
                acc[nt][0] = xpre[nt][0].x; acc[nt][1] = xpre[nt][0].y;
                acc[nt][2] = xpre[nt][1].x; acc[nt][3] = xpre[nt][1].y;
            }
            if (step + 1 < T_STEPS) {
                // gate on x_proj availability for step+1 (almost always passes)
                const int sp = (step + 1) >> 1;
                while (ld_acq(&g_xpcnt[sp]) < (unsigned)TILES_PER_SP) { }
                const float* xpn = g_xp + (size_t)(step + 1) * B_ * 2048;
                #pragma unroll
                for (int nt = 0; nt < 4; ++nt) {
                    xpre[nt][0] = __ldcs(reinterpret_cast<const float2*>(
                        xpn + (size_t)rb0 * 2048 + nt * 512 + col0));
                    xpre[nt][1] = __ldcs(reinterpret_cast<const float2*>(
                        xpn + (size_t)rb1 * 2048 + nt * 512 + col0));
                }
            }
        } else {
            #pragma unroll
            for (int nt = 0; nt < 4; ++nt)
                #pragma unroll
                for (int ci = 0; ci < 4; ++ci) acc[nt][ci] = 0.0f;
        }

        // poll this half's gating CTAs (h readiness)
        {
            int src_cta = half * 32 + lane;
            bool skip = (src_cta == cta);
            bool done;
            do {
                unsigned v = skip ? ~0u : ld_acq(&g_flags[src_cta * 32]);
                done = __all_sync(0xffffffffu, v >= want);
            } while (!done);
        }

        // copy this warp's rows of its 2 k-blocks
        #pragma unroll
        for (int i2 = 0; i2 < 2; ++i2) {
            int b = half * 2 + i2;
            const float* src = hsrc + b * AS_BLK_FLOATS + wrow * 16 * 128;
            unsigned     dst = as_base + (unsigned)b * 32768u
                               + (unsigned)(wrow * 16 * 128) * 4u;
            #pragma unroll
            for (int i = 0; i < 16; ++i) {
                int off = (i * 32 + lane) * 4;
                cp16(dst + (unsigned)off * 4u, src + off);
            }
            asm volatile("cp.async.commit_group;\n" ::: "memory");
        }

        // mma over this warp's 2 k-blocks
        #pragma unroll
        for (int i2 = 0; i2 < 2; ++i2) {
            if (i2 == 0) asm volatile("cp.async.wait_group 1;\n" ::: "memory");
            else         asm volatile("cp.async.wait_group 0;\n" ::: "memory");
            const int blk = half * 2 + i2;
            const float* Ab = Asb + blk * AS_BLK_FLOATS;
            #pragma unroll 4
            for (int ks = 0; ks < KS_PER_BLK; ++ks) {
                const int kb = ks * 8;
                const int ksg = blk * KS_PER_BLK + ks;
                float2 aA = *reinterpret_cast<const float2*>(
                    Ab + rb0 * 128 + ((kb + 2 * t) ^ swz));
                float2 aB = *reinterpret_cast<const float2*>(
                    Ab + rb1 * 128 + ((kb + 2 * t) ^ swz));
                unsigned a0 = __float_as_uint(aA.x);
                unsigned a1 = __float_as_uint(aB.x);
                unsigned a2 = __float_as_uint(aA.y);
                unsigned a3 = __float_as_uint(aB.y);
                #pragma unroll
                for (int nt = 0; nt < 4; ++nt) {
                    uint2 b2 = *reinterpret_cast<const uint2*>(
                        WpU + ((size_t)(ksg * 4 + nt) * 32 + lane) * 2);
                    mma8(acc[nt], a0, a1, a2, a3, b2.x, b2.y);
                }
            }
        }

        // half 1: deposit partials
        float* pb = Pbuf + (step & 1) * 128 * PB_STRIDE + pidx * PB_STRIDE;
        if (half == 1) {
            #pragma unroll
            for (int nt = 0; nt < 4; ++nt)
                *reinterpret_cast<float4*>(pb + nt * 4) =
                    make_float4(acc[nt][0], acc[nt][1], acc[nt][2], acc[nt][3]);
        }

        __syncthreads();

        if (half == 0) {
            #pragma unroll
            for (int nt = 0; nt < 4; ++nt) {
                float4 p = *reinterpret_cast<const float4*>(pb + nt * 4);
                acc[nt][0] += p.x; acc[nt][1] += p.y;
                acc[nt][2] += p.z; acc[nt][3] += p.w;
            }
            #pragma unroll
            for (int ci = 0; ci < 4; ++ci) {
                const int rb  = (ci >= 2) ? rb1 : rb0;
                const int col = col0 + (ci & 1);
                float iv = sigm_(acc[0][ci]);
                float fv = sigm_(acc[1][ci]);
                float gv = tanh_(acc[2][ci]);
                float ov = sigm_(acc[3][ci]);
                float c  = fv * creg[ci] + iv * gv;
                creg[ci] = c;
                float h  = ov * tanh_(c);
                __stcg(hnext + (col >> 7) * AS_BLK_FLOATS + hpos(rb, col), tf32r(h));
                if (step == T_STEPS - 1) {
                    out[rb * H_ + col]           = h;
                    out[B_ * H_ + rb * H_ + col] = c;
                }
            }
            asm volatile("bar.sync 1, 128;" ::: "memory");
            if (tid == 0) {
                __threadfence();
                st_rel(&g_flags[cta * 32], (unsigned)(step + 1));
            }
        }

        cur = nxt;
    }
}

// ---------------- launch --------------------------------------
extern "C" void kernel_launch(void* const* d_in, const int* in_sizes, int n_in,
                              void* d_out, int out_size)
{
    const float* x   = (const float*)d_in[0];
    const float* h0  = (const float*)d_in[1];
    const float* c0  = (const float*)d_in[2];
    const float* Wii = (const float*)d_in[3];
    const float* Whi = (const float*)d_in[4];
    const float* bi  = (const float*)d_in[5];
    const float* Wif = (const float*)d_in[6];
    const float* Whf = (const float*)d_in[7];
    const float* bf  = (const float*)d_in[8];
    const float* Wig = (const float*)d_in[9];
    const float* Whg = (const float*)d_in[10];
    const float* bg  = (const float*)d_in[11];
    const float* Wio = (const float*)d_in[12];
    const float* Who = (const float*)d_in[13];
    const float* bo  = (const float*)d_in[14];
    float* out = (float*)d_out;

    cudaFuncSetAttribute(lstm_fused,
                         cudaFuncAttributeMaxDynamicSharedMemorySize, SMEM_BYTES);

    cvt_init<<<2048, 256>>>(reinterpret_cast<const float4*>(x), h0,
                            Wii, Wif, Wig, Wio);
    lstm_fused<<<G_TOTAL, NTHREADS, SMEM_BYTES>>>(
        c0, Whi, Whf, Whg, Who, bi, bf, bg, bo, out);
}